// round 8
// baseline (speedup 1.0000x reference)
#include <cuda_runtime.h>
#include <cuda_fp16.h>
#include <cstdint>

#define NDIM 4096
#define NB   32
#define BSZ  128
#define LAT  64
#define NCOL (NB * LAT)   // 2048

// Static device scratch.
__device__ __half g_Wh[(size_t)NDIM * NDIM];          // W fp16 (GEMM operand)
__device__ __half g_Mt[2][(size_t)NCOL * NDIM];       // Mt[n,k]=M[k,n]; [0]=hi,[1]=lo fp16
__device__ __half g_WeTh[2][LAT * BSZ];               // WeT[t,c]=We[c,t]; hi/lo fp16
__device__ float g_Y[(size_t)NDIM * NCOL];
__device__ float g_What[(size_t)NDIM * NDIM];         // read only where flag set
__device__ unsigned char g_flags[NDIM * NB];
__device__ int g_rowbad[NDIM];

// ---------------------------------------------------------------------------
// Base-target helpers (sm_80+)
// ---------------------------------------------------------------------------
__device__ __forceinline__ uint32_t smem_u32(const void* p) {
    uint32_t a;
    asm("{ .reg .u64 t; cvta.to.shared.u64 t, %1; cvt.u32.u64 %0, t; }" : "=r"(a) : "l"(p));
    return a;
}
#define CP_ASYNC16(s, g) asm volatile("cp.async.cg.shared.global [%0], [%1], 16;" :: "r"(s), "l"(g))
#define CP_COMMIT()      asm volatile("cp.async.commit_group;" ::: "memory")
#define CP_WAIT(n)       asm volatile("cp.async.wait_group %0;" :: "n"(n) : "memory")

__device__ __forceinline__ void ldm_x4(uint32_t addr, uint32_t r[4]) {
    asm volatile("ldmatrix.sync.aligned.m8n8.x4.shared.b16 {%0,%1,%2,%3}, [%4];"
                 : "=r"(r[0]), "=r"(r[1]), "=r"(r[2]), "=r"(r[3]) : "r"(addr));
}
__device__ __forceinline__ void mma_f16(float* c, const uint32_t a[4], uint32_t b0, uint32_t b1) {
    asm volatile(
        "mma.sync.aligned.m16n8k16.row.col.f32.f16.f16.f32 "
        "{%0,%1,%2,%3}, {%4,%5,%6,%7}, {%8,%9}, {%0,%1,%2,%3};"
        : "+f"(c[0]), "+f"(c[1]), "+f"(c[2]), "+f"(c[3])
        : "r"(a[0]), "r"(a[1]), "r"(a[2]), "r"(a[3]), "r"(b0), "r"(b1));
}
__device__ __forceinline__ void split2h(float v, __half& hi, __half& lo) {
    hi = __float2half_rn(v);
    lo = __float2half_rn(v - __half2float(hi));
}

#define RS 80   // smem row stride: 32 fp16 (64B) + 16B pad -> conflict-free ldmatrix

// ---------------------------------------------------------------------------
// kernPrep: W fp32 -> fp16 (blocks 0..8191), WeT split (blocks 8192..8223).
// ---------------------------------------------------------------------------
__global__ void kernPrep(const float* __restrict__ W, const float* __restrict__ We) {
    int b = blockIdx.x;
    if (b < 8192) {
        size_t idx = (size_t)b * 256 + threadIdx.x;   // per 8 elems
        const float4* s = reinterpret_cast<const float4*>(W) + idx * 2;
        float4 a = s[0], c = s[1];
        float v[8] = {a.x, a.y, a.z, a.w, c.x, c.y, c.z, c.w};
        __half h[8];
#pragma unroll
        for (int q = 0; q < 8; ++q) h[q] = __float2half_rn(v[q]);
        *reinterpret_cast<uint4*>(g_Wh + idx * 8) = *reinterpret_cast<uint4*>(h);
    } else {
        int idx = (b - 8192) * 256 + threadIdx.x;     // 0..8191
        int t = idx >> 7, c = idx & 127;
        __half h, l;
        split2h(We[c * LAT + t], h, l);
        g_WeTh[0][idx] = h;
        g_WeTh[1][idx] = l;
    }
}

// ---------------------------------------------------------------------------
// kernG: builds the FULL Mt (fp16 hi+lo).
//   kt > j : G block via 3-term split fp16 HMMA (residual ~2^-21)
//   kt == j: diagonal We block (split);  kt < j : zero fill
// Grid (32 kt, 32 j), 128 threads. smem 30720 B.
// ---------------------------------------------------------------------------
__global__ void __launch_bounds__(128, 4) kernG(const float* __restrict__ L,
                                                const float* __restrict__ We) {
    int kt = blockIdx.x, j = blockIdx.y;
    int tid = threadIdx.x;
    int jn = j * LAT, s = j * BSZ;

    if (kt < j) {
        uint4 z = make_uint4(0, 0, 0, 0);
        for (int i = tid; i < 64 * 16; i += 128) {
            int rr = i >> 4, c = i & 15;
            size_t o = (size_t)(jn + rr) * NDIM + kt * BSZ + c * 8;
            *reinterpret_cast<uint4*>(g_Mt[0] + o) = z;
            *reinterpret_cast<uint4*>(g_Mt[1] + o) = z;
        }
        return;
    }
    if (kt == j) {
        for (int n = 0; n < LAT; ++n) {
            __half h, l;
            split2h(We[tid * LAT + n], h, l);
            size_t o = (size_t)(jn + n) * NDIM + s + tid;
            g_Mt[0][o] = h;
            g_Mt[1][o] = l;
        }
        return;
    }

    extern __shared__ __align__(128) char sm[];
    uint32_t sb = smem_u32(sm);
    uint32_t sA[2] = {sb, sb + 5120};
    uint32_t sB[2] = {sb + 10240, sb + 20480};
    int wid = tid >> 5, lane = tid & 31;
    int k0g = kt * BSZ;
    int wm = (wid & 1) * 32, wn = (wid >> 1) * 64;

    float acc[2][8][4];
#pragma unroll
    for (int i = 0; i < 2; ++i)
#pragma unroll
        for (int q = 0; q < 8; ++q)
#pragma unroll
            for (int z = 0; z < 4; ++z) acc[i][q][z] = 0.f;

    for (int it = 0; it < 4; ++it) {            // K=128, BK=32
        int kk = it * 32;
#pragma unroll
        for (int q = 0; q < 4; ++q) {
            int id = tid + q * 128;
            int prec = id >> 8, rem = id & 255, row = rem >> 2, ch = rem & 3;
            CP_ASYNC16(sA[prec] + row * RS + ch * 16,
                       g_WeTh[prec] + row * BSZ + kk + ch * 8);
        }
        CP_COMMIT();
#pragma unroll
        for (int q = 0; q < 8; ++q) {           // B: L fp32 -> split fp16 in-reg
            int id = tid + q * 128;
            int row = id >> 3, c = (id & 7) * 4;
            float4 v = *reinterpret_cast<const float4*>(
                L + (size_t)(k0g + row) * NDIM + s + kk + c);
            __half h0, l0, h1, l1, h2, l2, h3, l3;
            split2h(v.x, h0, l0); split2h(v.y, h1, l1);
            split2h(v.z, h2, l2); split2h(v.w, h3, l3);
            __half2 hA = __halves2half2(h0, h1), hB = __halves2half2(h2, h3);
            __half2 lA = __halves2half2(l0, l1), lB = __halves2half2(l2, l3);
            uint2 uh, ul;
            uh.x = *reinterpret_cast<uint32_t*>(&hA); uh.y = *reinterpret_cast<uint32_t*>(&hB);
            ul.x = *reinterpret_cast<uint32_t*>(&lA); ul.y = *reinterpret_cast<uint32_t*>(&lB);
            *reinterpret_cast<uint2*>(sm + 10240 + row * RS + c * 2) = uh;
            *reinterpret_cast<uint2*>(sm + 20480 + row * RS + c * 2) = ul;
        }
        CP_WAIT(0);
        __syncthreads();

#pragma unroll
        for (int ks = 0; ks < 2; ++ks) {
            uint32_t ah[2][4];
#pragma unroll
            for (int mf = 0; mf < 2; ++mf)
                ldm_x4(sA[0] + (wm + mf * 16 + (lane & 15)) * RS + ks * 32 + (lane >> 4) * 16, ah[mf]);
            uint32_t bh[8][2];
#pragma unroll
            for (int p = 0; p < 4; ++p) {
                uint32_t r[4];
                int g = lane >> 3;
                int row = wn + p * 16 + ((g >> 1) << 3) + (lane & 7);
                ldm_x4(sB[0] + row * RS + ks * 32 + (g & 1) * 16, r);
                bh[p * 2][0] = r[0]; bh[p * 2][1] = r[1];
                bh[p * 2 + 1][0] = r[2]; bh[p * 2 + 1][1] = r[3];
            }
#pragma unroll
            for (int mf = 0; mf < 2; ++mf)
#pragma unroll
                for (int nf = 0; nf < 8; ++nf)
                    mma_f16(acc[mf][nf], ah[mf], bh[nf][0], bh[nf][1]);
            uint32_t al[2][4];
#pragma unroll
            for (int mf = 0; mf < 2; ++mf)
                ldm_x4(sA[1] + (wm + mf * 16 + (lane & 15)) * RS + ks * 32 + (lane >> 4) * 16, al[mf]);
#pragma unroll
            for (int mf = 0; mf < 2; ++mf)
#pragma unroll
                for (int nf = 0; nf < 8; ++nf)
                    mma_f16(acc[mf][nf], al[mf], bh[nf][0], bh[nf][1]);
            uint32_t bl[8][2];
#pragma unroll
            for (int p = 0; p < 4; ++p) {
                uint32_t r[4];
                int g = lane >> 3;
                int row = wn + p * 16 + ((g >> 1) << 3) + (lane & 7);
                ldm_x4(sB[1] + row * RS + ks * 32 + (g & 1) * 16, r);
                bl[p * 2][0] = r[0]; bl[p * 2][1] = r[1];
                bl[p * 2 + 1][0] = r[2]; bl[p * 2 + 1][1] = r[3];
            }
#pragma unroll
            for (int mf = 0; mf < 2; ++mf)
#pragma unroll
                for (int nf = 0; nf < 8; ++nf)
                    mma_f16(acc[mf][nf], ah[mf], bl[nf][0], bl[nf][1]);
        }
        __syncthreads();
    }

#pragma unroll
    for (int mf = 0; mf < 2; ++mf) {
        int t0 = wm + mf * 16 + (lane >> 2);
#pragma unroll
        for (int nf = 0; nf < 8; ++nf) {
            int kr = wn + nf * 8 + 2 * (lane & 3);
            __half h0, l0, h1, l1, h2, l2, h3, l3;
            split2h(acc[mf][nf][0], h0, l0);
            split2h(acc[mf][nf][1], h1, l1);
            split2h(acc[mf][nf][2], h2, l2);
            split2h(acc[mf][nf][3], h3, l3);
            size_t o0 = (size_t)(jn + t0) * NDIM + k0g + kr;
            size_t o1 = (size_t)(jn + t0 + 8) * NDIM + k0g + kr;
            *reinterpret_cast<__half2*>(g_Mt[0] + o0) = __halves2half2(h0, h1);
            *reinterpret_cast<__half2*>(g_Mt[1] + o0) = __halves2half2(l0, l1);
            *reinterpret_cast<__half2*>(g_Mt[0] + o1) = __halves2half2(h2, h3);
            *reinterpret_cast<__half2*>(g_Mt[1] + o1) = __halves2half2(l2, l3);
        }
    }
}

// ---------------------------------------------------------------------------
// kernGemmY: Y = W @ M^T, single fp16 HMMA pass, fp32 accum.
// BM=128 BN=128 BK=32, 256 thr. Double-buffered cp.async. k starts at n0*2.
// ---------------------------------------------------------------------------
__global__ void __launch_bounds__(256, 2) kernGemmY() {
    extern __shared__ __align__(128) char sm[];
    const int TSZ = 128 * RS;                 // 10240
    const int STG = 2 * TSZ;                  // 20480 per stage (A + B)
    uint32_t sb = smem_u32(sm);
    int tid = threadIdx.x, wid = tid >> 5, lane = tid & 31;
    int m0 = blockIdx.x * 128, n0 = blockIdx.y * 128;
    int kst = n0 * 2;
    int niter = (NDIM - kst) / 32;
    int wm = (wid & 1) * 64, wn = (wid >> 1) * 32;

    float acc[4][4][4];
#pragma unroll
    for (int i = 0; i < 4; ++i)
#pragma unroll
        for (int q = 0; q < 4; ++q)
#pragma unroll
            for (int z = 0; z < 4; ++z) acc[i][q][z] = 0.f;

    {
        uint32_t s_a = sb, s_b = sb + TSZ;
#pragma unroll
        for (int q = 0; q < 2; ++q) {
            int id = tid + q * 256, row = id >> 2, ch = id & 3;
            CP_ASYNC16(s_a + row * RS + ch * 16, g_Wh + (size_t)(m0 + row) * NDIM + kst + ch * 8);
            CP_ASYNC16(s_b + row * RS + ch * 16, g_Mt[0] + (size_t)(n0 + row) * NDIM + kst + ch * 8);
        }
        CP_COMMIT();
    }

    for (int it = 0; it < niter; ++it) {
        if (it + 1 < niter) {
            int k0 = kst + (it + 1) * 32;
            uint32_t s_a = sb + ((it + 1) & 1) * STG, s_b = s_a + TSZ;
#pragma unroll
            for (int q = 0; q < 2; ++q) {
                int id = tid + q * 256, row = id >> 2, ch = id & 3;
                CP_ASYNC16(s_a + row * RS + ch * 16, g_Wh + (size_t)(m0 + row) * NDIM + k0 + ch * 8);
                CP_ASYNC16(s_b + row * RS + ch * 16, g_Mt[0] + (size_t)(n0 + row) * NDIM + k0 + ch * 8);
            }
            CP_COMMIT();
            CP_WAIT(1);
        } else {
            CP_WAIT(0);
        }
        __syncthreads();
        uint32_t s_a = sb + (it & 1) * STG, s_b = s_a + TSZ;
#pragma unroll
        for (int ks = 0; ks < 2; ++ks) {
            uint32_t a[4][4];
#pragma unroll
            for (int mf = 0; mf < 4; ++mf)
                ldm_x4(s_a + (wm + mf * 16 + (lane & 15)) * RS + ks * 32 + (lane >> 4) * 16, a[mf]);
            uint32_t b[4][2];
#pragma unroll
            for (int p = 0; p < 2; ++p) {
                uint32_t r[4];
                int g = lane >> 3;
                int row = wn + p * 16 + ((g >> 1) << 3) + (lane & 7);
                ldm_x4(s_b + row * RS + ks * 32 + (g & 1) * 16, r);
                b[p * 2][0] = r[0]; b[p * 2][1] = r[1];
                b[p * 2 + 1][0] = r[2]; b[p * 2 + 1][1] = r[3];
            }
#pragma unroll
            for (int mf = 0; mf < 4; ++mf)
#pragma unroll
                for (int nf = 0; nf < 4; ++nf)
                    mma_f16(acc[mf][nf], a[mf], b[nf][0], b[nf][1]);
        }
        __syncthreads();
    }

#pragma unroll
    for (int mf = 0; mf < 4; ++mf) {
        int row = m0 + wm + mf * 16 + (lane >> 2);
#pragma unroll
        for (int nf = 0; nf < 4; ++nf) {
            int col = n0 + wn + nf * 8 + 2 * (lane & 3);
            *reinterpret_cast<float2*>(g_Y + (size_t)row * NCOL + col) =
                make_float2(acc[mf][nf][0], acc[mf][nf][1]);
            *reinterpret_cast<float2*>(g_Y + (size_t)(row + 8) * NCOL + col) =
                make_float2(acc[mf][nf][2], acc[mf][nf][3]);
        }
    }
}

// ---------------------------------------------------------------------------
// kernScan: per-row triviality check (parallel, streaming).
// Row r is "bad" iff any element rounds nonzero OR is within 5e-3 of a
// +-0.5 boundary (fp16-hh y-error max ~4e-4 -> 12x margin). If a row is NOT
// bad, the all-zero solution is exact (feedback is row-local + causal).
// Also zeroes g_flags for the row.
// ---------------------------------------------------------------------------
__global__ void kernScan(const float* __restrict__ rn) {
    int r = blockIdx.x;
    int tid = threadIdx.x;
    __shared__ int bad;
    if (tid == 0) bad = 0;
    __syncthreads();
    float inv = 1.0f / rn[r];
    int lb = 0;
    const float4* yp = reinterpret_cast<const float4*>(g_Y + (size_t)r * NCOL);
    for (int i = tid; i < NCOL / 4; i += 256) {
        float4 v = yp[i];
        float ya[4] = {v.x * inv, v.y * inv, v.z * inv, v.w * inv};
#pragma unroll
        for (int q = 0; q < 4; ++q) {
            float yh = rintf(ya[q]);
            if (yh != 0.f || fabsf(ya[q] - yh) > 0.495f) lb = 1;
        }
    }
    if (lb) bad = 1;          // benign race
    if (tid < NB) g_flags[r * NB + tid] = 0;
    __syncthreads();
    if (tid == 0) g_rowbad[r] = bad;
}

// ---------------------------------------------------------------------------
// kernFix: exact fp32 sequential recurrence, ONLY for bad rows (expected 0).
// One block per row, 256 threads (8 warps). Per block jb: warp w computes
// 8 n-values by lane-strided exact dot of (W - W_hat)[r, s:] with M[:, n]
// (Mt hi+lo, ~fp32 accurate), then quantize, synthesize x_hat, write W_hat
// + flags. __syncthreads orders the row-local global W_hat writes.
// ---------------------------------------------------------------------------
__global__ void kernFix(const float* __restrict__ rn, const float* __restrict__ Wd,
                        const float* __restrict__ W) {
    int r = blockIdx.x;
    if (!g_rowbad[r]) return;
    int tid = threadIdx.x, wid = tid >> 5, lane = tid & 31;
    __shared__ float s_yh[LAT];
    __shared__ int s_nz;
    float rnv = rn[r];
    const float* wr = W + (size_t)r * NDIM;
    float* whr = g_What + (size_t)r * NDIM;

    for (int jb = NB - 1; jb >= 0; --jb) {
        int s = jb * BSZ, e = s + BSZ, jn = jb * LAT;
        if (tid == 0) s_nz = 0;
        __syncthreads();
#pragma unroll 1
        for (int q = 0; q < 8; ++q) {
            int n = wid * 8 + q;
            size_t mo = (size_t)(jn + n) * NDIM;
            float acc = 0.f;
            for (int k = s + lane; k < NDIM; k += 32) {
                float wv = wr[k];
                if (k >= e) wv -= whr[k];
                float mv = __half2float(g_Mt[0][mo + k]) + __half2float(g_Mt[1][mo + k]);
                acc = fmaf(wv, mv, acc);
            }
#pragma unroll
            for (int o = 16; o; o >>= 1) acc += __shfl_xor_sync(0xFFFFFFFFu, acc, o);
            if (lane == 0) {
                float yh = rintf(acc / rnv);
                s_yh[n] = yh;
                if (yh != 0.f) s_nz = 1;   // benign race
            }
        }
        __syncthreads();
        int nz = s_nz;
        if (tid < BSZ) {
            float x = 0.f;
            if (nz) {
                for (int tt = 0; tt < LAT; ++tt)
                    x = fmaf(s_yh[tt], Wd[tt * BSZ + tid], x);
            }
            whr[s + tid] = x;   // always write: clears stale data for this row
        }
        if (tid == 0) g_flags[r * NB + jb] = (unsigned char)(nz ? 1 : 0);
        __syncthreads();
    }
}

// ---------------------------------------------------------------------------
// kernOut: out = bias + x @ (W_hat * rn)^T, skipping exactly-zero k-blocks.
// ---------------------------------------------------------------------------
__global__ void kernOut(const float* __restrict__ x, const float* __restrict__ rn,
                        const float* __restrict__ bias, float* __restrict__ out) {
    __shared__ __align__(16) float xs[16][64];
    __shared__ __align__(16) float ws[16][64];
    __shared__ unsigned char shf[NB];

    int b0 = blockIdx.x * 64;
    int m0 = blockIdx.y * 64;
    int tid = threadIdx.x;

    if (tid < NB) {
        unsigned char f = 0;
        for (int mm = 0; mm < 64; ++mm) f |= g_flags[(m0 + mm) * NB + tid];
        shf[tid] = f;
    }
    __syncthreads();

    int tr = tid >> 4, tc = tid & 15;
    int l_r = tid >> 2, l_q = (tid & 3) * 4;

    float acc[4][4];
#pragma unroll
    for (int i = 0; i < 4; ++i)
#pragma unroll
        for (int q = 0; q < 4; ++q) acc[i][q] = 0.f;

    float rnm = rn[m0 + l_r];

    for (int jj = 0; jj < NB; ++jj) {
        if (!shf[jj]) continue;
        for (int k0 = 0; k0 < BSZ; k0 += 16) {
            float4 xv = *reinterpret_cast<const float4*>(x + (size_t)(b0 + l_r) * NDIM + jj * BSZ + k0 + l_q);
            xs[l_q + 0][l_r] = xv.x; xs[l_q + 1][l_r] = xv.y;
            xs[l_q + 2][l_r] = xv.z; xs[l_q + 3][l_r] = xv.w;
            float4 wv = *reinterpret_cast<const float4*>(g_What + (size_t)(m0 + l_r) * NDIM + jj * BSZ + k0 + l_q);
            ws[l_q + 0][l_r] = wv.x * rnm; ws[l_q + 1][l_r] = wv.y * rnm;
            ws[l_q + 2][l_r] = wv.z * rnm; ws[l_q + 3][l_r] = wv.w * rnm;
            __syncthreads();
#pragma unroll
            for (int kk = 0; kk < 16; ++kk) {
                float4 a4 = *reinterpret_cast<const float4*>(&xs[kk][tr * 4]);
                float4 b4 = *reinterpret_cast<const float4*>(&ws[kk][tc * 4]);
                float a[4] = {a4.x, a4.y, a4.z, a4.w};
                float b[4] = {b4.x, b4.y, b4.z, b4.w};
#pragma unroll
                for (int i = 0; i < 4; ++i)
#pragma unroll
                    for (int q = 0; q < 4; ++q)
                        acc[i][q] = fmaf(a[i], b[q], acc[i][q]);
            }
            __syncthreads();
        }
    }

#pragma unroll
    for (int i = 0; i < 4; ++i) {
        int b = b0 + tr * 4 + i;
#pragma unroll
        for (int q = 0; q < 4; ++q) {
            int m = m0 + tc * 4 + q;
            out[(size_t)b * NDIM + m] = bias[m] + acc[i][q];
        }
    }
}

// ---------------------------------------------------------------------------
// kernel_launch: inputs (metadata order): x, weight, bias, row_norm, L, We, Wd
// ---------------------------------------------------------------------------
extern "C" void kernel_launch(void* const* d_in, const int* in_sizes, int n_in,
                              void* d_out, int out_size) {
    (void)in_sizes; (void)n_in; (void)out_size;
    const float* x      = (const float*)d_in[0];
    const float* weight = (const float*)d_in[1];
    const float* bias   = (const float*)d_in[2];
    const float* rn     = (const float*)d_in[3];
    const float* L      = (const float*)d_in[4];
    const float* We     = (const float*)d_in[5];
    const float* Wd     = (const float*)d_in[6];
    float* out          = (float*)d_out;

    kernPrep<<<8224, 256>>>(weight, We);                  // [0] W->fp16, WeT split
    kernG<<<dim3(32, 32), 128, 30720>>>(L, We);           // [1] full Mt (split fp16 HMMA)
    kernGemmY<<<dim3(32, 16), 256, 40960>>>();            // [2] Y = W @ M (fp16 hh)
    kernScan<<<NDIM, 256>>>(rn);                          // [3] per-row triviality scan
    kernFix<<<NDIM, 256>>>(rn, Wd, weight);               // [4] exact path, bad rows only
    kernOut<<<dim3(64, 64), 256>>>(x, rn, bias, out);     // [5] output GEMM
}

// round 9
// speedup vs baseline: 6.1083x; 6.1083x over previous
#include <cuda_runtime.h>
#include <cuda_fp16.h>
#include <cstdint>

#define NDIM 4096
#define NB   32
#define BSZ  128
#define LAT  64
#define NCOL (NB * LAT)   // 2048
#define MAXIT (NDIM * NB)

// Static device scratch.
__device__ __half g_Wh[2][(size_t)NDIM * NDIM];       // W fp16 hi/lo split
__device__ __half g_Mt[2][(size_t)NCOL * NDIM];       // Mt[n,k]=M[k,n]; hi/lo fp16
__device__ __half g_WeTh[2][LAT * BSZ];               // WeT[t,c]=We[c,t]; hi/lo
__device__ float g_Y[(size_t)NDIM * NCOL];
__device__ float g_H[(size_t)NB * NB * LAT * LAT];    // H[jb][jj][u][t] (jj>jb valid)
__device__ float g_What[(size_t)NDIM * NDIM];         // valid only where flag set
__device__ unsigned char g_flags[NDIM * NB];
__device__ int g_cnt;
__device__ int g_items[MAXIT];
__device__ float g_yhl[(size_t)MAXIT * LAT];

// ---------------------------------------------------------------------------
// Base-target helpers (sm_80+)
// ---------------------------------------------------------------------------
__device__ __forceinline__ uint32_t smem_u32(const void* p) {
    uint32_t a;
    asm("{ .reg .u64 t; cvta.to.shared.u64 t, %1; cvt.u32.u64 %0, t; }" : "=r"(a) : "l"(p));
    return a;
}
#define CP_ASYNC16(s, g) asm volatile("cp.async.cg.shared.global [%0], [%1], 16;" :: "r"(s), "l"(g))
#define CP_COMMIT()      asm volatile("cp.async.commit_group;" ::: "memory")
#define CP_WAIT(n)       asm volatile("cp.async.wait_group %0;" :: "n"(n) : "memory")

__device__ __forceinline__ void ldm_x4(uint32_t addr, uint32_t r[4]) {
    asm volatile("ldmatrix.sync.aligned.m8n8.x4.shared.b16 {%0,%1,%2,%3}, [%4];"
                 : "=r"(r[0]), "=r"(r[1]), "=r"(r[2]), "=r"(r[3]) : "r"(addr));
}
__device__ __forceinline__ void mma_f16(float* c, const uint32_t a[4], uint32_t b0, uint32_t b1) {
    asm volatile(
        "mma.sync.aligned.m16n8k16.row.col.f32.f16.f16.f32 "
        "{%0,%1,%2,%3}, {%4,%5,%6,%7}, {%8,%9}, {%0,%1,%2,%3};"
        : "+f"(c[0]), "+f"(c[1]), "+f"(c[2]), "+f"(c[3])
        : "r"(a[0]), "r"(a[1]), "r"(a[2]), "r"(a[3]), "r"(b0), "r"(b1));
}
__device__ __forceinline__ void split2h(float v, __half& hi, __half& lo) {
    hi = __float2half_rn(v);
    lo = __float2half_rn(v - __half2float(hi));
}

#define RS 80   // smem row stride: 32 fp16 (64B) + 16B pad

// ---------------------------------------------------------------------------
// kernPrep: W fp32 -> fp16 hi/lo (blocks 0..8191), WeT split (8192..8223).
// ---------------------------------------------------------------------------
__global__ void kernPrep(const float* __restrict__ W, const float* __restrict__ We) {
    int b = blockIdx.x;
    if (b < 8192) {
        size_t idx = (size_t)b * 256 + threadIdx.x;   // per 8 elems
        const float4* s = reinterpret_cast<const float4*>(W) + idx * 2;
        float4 a = s[0], c = s[1];
        float v[8] = {a.x, a.y, a.z, a.w, c.x, c.y, c.z, c.w};
        __half h[8], l[8];
#pragma unroll
        for (int q = 0; q < 8; ++q) split2h(v[q], h[q], l[q]);
        *reinterpret_cast<uint4*>(g_Wh[0] + idx * 8) = *reinterpret_cast<uint4*>(h);
        *reinterpret_cast<uint4*>(g_Wh[1] + idx * 8) = *reinterpret_cast<uint4*>(l);
    } else {
        int idx = (b - 8192) * 256 + threadIdx.x;     // 0..8191
        int t = idx >> 7, c = idx & 127;
        __half h, l;
        split2h(We[c * LAT + t], h, l);
        g_WeTh[0][idx] = h;
        g_WeTh[1][idx] = l;
    }
}

// ---------------------------------------------------------------------------
// kernG: builds the FULL Mt (fp16 hi+lo).
//   kt > j : G block via 3-term split fp16 HMMA;  kt == j: diag We;  kt < j: 0
// Grid (32 kt, 32 j), 128 threads, smem 30720 B.
// ---------------------------------------------------------------------------
__global__ void __launch_bounds__(128, 4) kernG(const float* __restrict__ L,
                                                const float* __restrict__ We) {
    int kt = blockIdx.x, j = blockIdx.y;
    int tid = threadIdx.x;
    int jn = j * LAT, s = j * BSZ;

    if (kt < j) {
        uint4 z = make_uint4(0, 0, 0, 0);
        for (int i = tid; i < 64 * 16; i += 128) {
            int rr = i >> 4, c = i & 15;
            size_t o = (size_t)(jn + rr) * NDIM + kt * BSZ + c * 8;
            *reinterpret_cast<uint4*>(g_Mt[0] + o) = z;
            *reinterpret_cast<uint4*>(g_Mt[1] + o) = z;
        }
        return;
    }
    if (kt == j) {
        for (int n = 0; n < LAT; ++n) {
            __half h, l;
            split2h(We[tid * LAT + n], h, l);
            size_t o = (size_t)(jn + n) * NDIM + s + tid;
            g_Mt[0][o] = h;
            g_Mt[1][o] = l;
        }
        return;
    }

    extern __shared__ __align__(128) char sm[];
    uint32_t sb = smem_u32(sm);
    uint32_t sA[2] = {sb, sb + 5120};
    uint32_t sB[2] = {sb + 10240, sb + 20480};
    int wid = tid >> 5, lane = tid & 31;
    int k0g = kt * BSZ;
    int wm = (wid & 1) * 32, wn = (wid >> 1) * 64;

    float acc[2][8][4];
#pragma unroll
    for (int i = 0; i < 2; ++i)
#pragma unroll
        for (int q = 0; q < 8; ++q)
#pragma unroll
            for (int z = 0; z < 4; ++z) acc[i][q][z] = 0.f;

    for (int it = 0; it < 4; ++it) {            // K=128, BK=32
        int kk = it * 32;
#pragma unroll
        for (int q = 0; q < 4; ++q) {
            int id = tid + q * 128;
            int prec = id >> 8, rem = id & 255, row = rem >> 2, ch = rem & 3;
            CP_ASYNC16(sA[prec] + row * RS + ch * 16,
                       g_WeTh[prec] + row * BSZ + kk + ch * 8);
        }
        CP_COMMIT();
#pragma unroll
        for (int q = 0; q < 8; ++q) {           // B: L fp32 -> split fp16 in-reg
            int id = tid + q * 128;
            int row = id >> 3, c = (id & 7) * 4;
            float4 v = *reinterpret_cast<const float4*>(
                L + (size_t)(k0g + row) * NDIM + s + kk + c);
            __half h0, l0, h1, l1, h2, l2, h3, l3;
            split2h(v.x, h0, l0); split2h(v.y, h1, l1);
            split2h(v.z, h2, l2); split2h(v.w, h3, l3);
            __half2 hA = __halves2half2(h0, h1), hB = __halves2half2(h2, h3);
            __half2 lA = __halves2half2(l0, l1), lB = __halves2half2(l2, l3);
            uint2 uh, ul;
            uh.x = *reinterpret_cast<uint32_t*>(&hA); uh.y = *reinterpret_cast<uint32_t*>(&hB);
            ul.x = *reinterpret_cast<uint32_t*>(&lA); ul.y = *reinterpret_cast<uint32_t*>(&lB);
            *reinterpret_cast<uint2*>(sm + 10240 + row * RS + c * 2) = uh;
            *reinterpret_cast<uint2*>(sm + 20480 + row * RS + c * 2) = ul;
        }
        CP_WAIT(0);
        __syncthreads();

#pragma unroll
        for (int ks = 0; ks < 2; ++ks) {
            uint32_t ah[2][4];
#pragma unroll
            for (int mf = 0; mf < 2; ++mf)
                ldm_x4(sA[0] + (wm + mf * 16 + (lane & 15)) * RS + ks * 32 + (lane >> 4) * 16, ah[mf]);
            uint32_t bh[8][2];
#pragma unroll
            for (int p = 0; p < 4; ++p) {
                uint32_t r[4];
                int g = lane >> 3;
                int row = wn + p * 16 + ((g >> 1) << 3) + (lane & 7);
                ldm_x4(sB[0] + row * RS + ks * 32 + (g & 1) * 16, r);
                bh[p * 2][0] = r[0]; bh[p * 2][1] = r[1];
                bh[p * 2 + 1][0] = r[2]; bh[p * 2 + 1][1] = r[3];
            }
#pragma unroll
            for (int mf = 0; mf < 2; ++mf)
#pragma unroll
                for (int nf = 0; nf < 8; ++nf)
                    mma_f16(acc[mf][nf], ah[mf], bh[nf][0], bh[nf][1]);
            uint32_t al[2][4];
#pragma unroll
            for (int mf = 0; mf < 2; ++mf)
                ldm_x4(sA[1] + (wm + mf * 16 + (lane & 15)) * RS + ks * 32 + (lane >> 4) * 16, al[mf]);
#pragma unroll
            for (int mf = 0; mf < 2; ++mf)
#pragma unroll
                for (int nf = 0; nf < 8; ++nf)
                    mma_f16(acc[mf][nf], al[mf], bh[nf][0], bh[nf][1]);
            uint32_t bl[8][2];
#pragma unroll
            for (int p = 0; p < 4; ++p) {
                uint32_t r[4];
                int g = lane >> 3;
                int row = wn + p * 16 + ((g >> 1) << 3) + (lane & 7);
                ldm_x4(sB[1] + row * RS + ks * 32 + (g & 1) * 16, r);
                bl[p * 2][0] = r[0]; bl[p * 2][1] = r[1];
                bl[p * 2 + 1][0] = r[2]; bl[p * 2 + 1][1] = r[3];
            }
#pragma unroll
            for (int mf = 0; mf < 2; ++mf)
#pragma unroll
                for (int nf = 0; nf < 8; ++nf)
                    mma_f16(acc[mf][nf], ah[mf], bl[nf][0], bl[nf][1]);
        }
        __syncthreads();
    }

#pragma unroll
    for (int mf = 0; mf < 2; ++mf) {
        int t0 = wm + mf * 16 + (lane >> 2);
#pragma unroll
        for (int nf = 0; nf < 8; ++nf) {
            int kr = wn + nf * 8 + 2 * (lane & 3);
            __half h0, l0, h1, l1, h2, l2, h3, l3;
            split2h(acc[mf][nf][0], h0, l0);
            split2h(acc[mf][nf][1], h1, l1);
            split2h(acc[mf][nf][2], h2, l2);
            split2h(acc[mf][nf][3], h3, l3);
            size_t o0 = (size_t)(jn + t0) * NDIM + k0g + kr;
            size_t o1 = (size_t)(jn + t0 + 8) * NDIM + k0g + kr;
            *reinterpret_cast<__half2*>(g_Mt[0] + o0) = __halves2half2(h0, h1);
            *reinterpret_cast<__half2*>(g_Mt[1] + o0) = __halves2half2(l0, l1);
            *reinterpret_cast<__half2*>(g_Mt[0] + o1) = __halves2half2(h2, h3);
            *reinterpret_cast<__half2*>(g_Mt[1] + o1) = __halves2half2(l2, l3);
        }
    }
}

// ---------------------------------------------------------------------------
// kernGemmY: Y = W @ M^T, 3-term split fp16 HMMA (hh + lh + hl), fp32 accum.
// R6-measured structure (297us, 128 regs). BM=128 BN=128 BK=32, 256 thr.
// Single-stage smem 40960 B, 2 CTAs/SM. k starts at n0*2 (triangular M).
// ---------------------------------------------------------------------------
__global__ void __launch_bounds__(256, 2) kernGemmY() {
    extern __shared__ __align__(128) char sm[];
    const int TSZ = 128 * RS;                 // 10240
    uint32_t sb = smem_u32(sm);
    uint32_t sA[2] = {sb, sb + TSZ};
    uint32_t sB[2] = {sb + 2 * TSZ, sb + 3 * TSZ};
    int tid = threadIdx.x, wid = tid >> 5, lane = tid & 31;
    int m0 = blockIdx.x * 128, n0 = blockIdx.y * 128;
    int kst = n0 * 2;
    int niter = (NDIM - kst) / 32;
    int wm = (wid & 1) * 64, wn = (wid >> 1) * 32;

    float acc[4][4][4];
#pragma unroll
    for (int i = 0; i < 4; ++i)
#pragma unroll
        for (int q = 0; q < 4; ++q)
#pragma unroll
            for (int z = 0; z < 4; ++z) acc[i][q][z] = 0.f;

    for (int it = 0; it < niter; ++it) {
        int k0 = kst + it * 32;
#pragma unroll
        for (int q = 0; q < 4; ++q) {
            int id = tid + q * 256;
            int prec = id >> 9, rem = id & 511, row = rem >> 2, ch = rem & 3;
            CP_ASYNC16(sA[prec] + row * RS + ch * 16,
                       g_Wh[prec] + (size_t)(m0 + row) * NDIM + k0 + ch * 8);
            CP_ASYNC16(sB[prec] + row * RS + ch * 16,
                       g_Mt[prec] + (size_t)(n0 + row) * NDIM + k0 + ch * 8);
        }
        CP_COMMIT();
        CP_WAIT(0);
        __syncthreads();

#pragma unroll
        for (int ks = 0; ks < 2; ++ks) {
            uint32_t ah[4][4];
#pragma unroll
            for (int mf = 0; mf < 4; ++mf)
                ldm_x4(sA[0] + (wm + mf * 16 + (lane & 15)) * RS + ks * 32 + (lane >> 4) * 16, ah[mf]);
            uint32_t bh[4][2];
#pragma unroll
            for (int p = 0; p < 2; ++p) {
                uint32_t r[4];
                int g = lane >> 3;
                int row = wn + p * 16 + ((g >> 1) << 3) + (lane & 7);
                ldm_x4(sB[0] + row * RS + ks * 32 + (g & 1) * 16, r);
                bh[p * 2][0] = r[0]; bh[p * 2][1] = r[1];
                bh[p * 2 + 1][0] = r[2]; bh[p * 2 + 1][1] = r[3];
            }
#pragma unroll
            for (int mf = 0; mf < 4; ++mf)
#pragma unroll
                for (int nf = 0; nf < 4; ++nf)
                    mma_f16(acc[mf][nf], ah[mf], bh[nf][0], bh[nf][1]);
            uint32_t al[4][4];
#pragma unroll
            for (int mf = 0; mf < 4; ++mf)
                ldm_x4(sA[1] + (wm + mf * 16 + (lane & 15)) * RS + ks * 32 + (lane >> 4) * 16, al[mf]);
#pragma unroll
            for (int mf = 0; mf < 4; ++mf)
#pragma unroll
                for (int nf = 0; nf < 4; ++nf)
                    mma_f16(acc[mf][nf], al[mf], bh[nf][0], bh[nf][1]);
            uint32_t bl[4][2];
#pragma unroll
            for (int p = 0; p < 2; ++p) {
                uint32_t r[4];
                int g = lane >> 3;
                int row = wn + p * 16 + ((g >> 1) << 3) + (lane & 7);
                ldm_x4(sB[1] + row * RS + ks * 32 + (g & 1) * 16, r);
                bl[p * 2][0] = r[0]; bl[p * 2][1] = r[1];
                bl[p * 2 + 1][0] = r[2]; bl[p * 2 + 1][1] = r[3];
            }
#pragma unroll
            for (int mf = 0; mf < 4; ++mf)
#pragma unroll
                for (int nf = 0; nf < 4; ++nf)
                    mma_f16(acc[mf][nf], ah[mf], bl[nf][0], bl[nf][1]);
        }
        __syncthreads();
    }

#pragma unroll
    for (int mf = 0; mf < 4; ++mf) {
        int row = m0 + wm + mf * 16 + (lane >> 2);
#pragma unroll
        for (int nf = 0; nf < 4; ++nf) {
            int col = n0 + wn + nf * 8 + 2 * (lane & 3);
            *reinterpret_cast<float2*>(g_Y + (size_t)row * NCOL + col) =
                make_float2(acc[mf][nf][0], acc[mf][nf][1]);
            *reinterpret_cast<float2*>(g_Y + (size_t)(row + 8) * NCOL + col) =
                make_float2(acc[mf][nf][2], acc[mf][nf][3]);
        }
    }
}

// ---------------------------------------------------------------------------
// kernH: H[jb][jj][u][t] = sum_c Wd[u][c] * G_jb[jj*128+c][t], for jj > jb.
// G_jb col t = Mt[(jb*64+t)] hi+lo. Grid (32 jj, 32 jb), 256 thr.
// Also resets g_cnt (block (0,0)).
// ---------------------------------------------------------------------------
__global__ void kernH(const float* __restrict__ Wd) {
    int jj = blockIdx.x, jb = blockIdx.y;
    if (jj <= jb) {
        if (jj == 0 && jb == 0 && threadIdx.x == 0) g_cnt = 0;
        return;
    }
    __shared__ float Gs[BSZ][LAT];   // 32KB
    int tid = threadIdx.x;
    // load G block: Gs[c][t]
    for (int i = tid; i < BSZ * LAT; i += 256) {
        int c = i >> 6, t = i & 63;
        size_t o = (size_t)(jb * LAT + t) * NDIM + jj * BSZ + c;
        Gs[c][t] = __half2float(g_Mt[0][o]) + __half2float(g_Mt[1][o]);
    }
    __syncthreads();
    int t = tid & 63, ug = tid >> 6;
    size_t hb = (((size_t)jb * NB + jj) * LAT) * LAT;
#pragma unroll 1
    for (int uu = 0; uu < 16; ++uu) {
        int u = ug * 16 + uu;
        const float* wd = Wd + u * BSZ;
        float acc = 0.f;
#pragma unroll 8
        for (int c = 0; c < BSZ; ++c) acc = fmaf(wd[c], Gs[c][t], acc);
        g_H[hb + (size_t)u * LAT + t] = acc;
    }
}

// ---------------------------------------------------------------------------
// kernSteps: 32 fused sequential steps, ENTIRELY in 64-dim latent space.
// Block = 4 rows x 64 threads. yhat kept in shared; feedback = yhat @ H.
// Emits flags + work items (r,jb) with yhat payload for kernWhat.
// ---------------------------------------------------------------------------
__global__ void kernSteps(const float* __restrict__ rn) {
    int rloc = threadIdx.x >> 6, t = threadIdx.x & 63;
    int r = blockIdx.x * 4 + rloc;

    __shared__ float yh[4][NB][LAT];    // 32KB
    __shared__ int s_nz[4], s_idx[4];
    __shared__ unsigned char fl[4][NB];

    float rnv = rn[r];
    if (t < NB) fl[rloc][t] = 0;

    for (int jb = NB - 1; jb >= 0; --jb) {
        __syncthreads();
        if (t == 0) { s_nz[rloc] = 0; s_idx[rloc] = -1; }
        __syncthreads();

        float y = g_Y[(size_t)r * NCOL + jb * LAT + t];
        for (int jj = jb + 1; jj < NB; ++jj) {
            if (fl[rloc][jj]) {
                const float* hp = g_H + (((size_t)jb * NB + jj) * LAT) * LAT + t;
                const float* yv = yh[rloc][jj];
#pragma unroll 8
                for (int u = 0; u < LAT; ++u)
                    y -= yv[u] * hp[(size_t)u * LAT];
            }
        }
        float yhv = rintf(y / rnv);
        yh[rloc][jb][t] = yhv;
        if (yhv != 0.f) s_nz[rloc] = 1;       // benign race
        __syncthreads();

        int nz = s_nz[rloc];
        if (t == 0) {
            fl[rloc][jb] = (unsigned char)nz;
            g_flags[r * NB + jb] = (unsigned char)nz;
            if (nz) s_idx[rloc] = atomicAdd(&g_cnt, 1);
        }
        __syncthreads();
        if (nz) {
            int idx = s_idx[rloc];
            if (t == 0) g_items[idx] = (r << 5) | jb;
            g_yhl[(size_t)idx * LAT + t] = yhv;
        }
    }
}

// ---------------------------------------------------------------------------
// kernWhat: materialize W_hat blocks for flagged items only.
// Grid 1024 fixed; each block strides the item list. 128 threads = cols.
// ---------------------------------------------------------------------------
__global__ void kernWhat(const float* __restrict__ Wd) {
    __shared__ float s_y[LAT];
    int tid = threadIdx.x;
    int cnt = g_cnt;
    for (int i = blockIdx.x; i < cnt; i += gridDim.x) {
        int item = g_items[i];
        int r = item >> 5, jb = item & 31;
        if (tid < LAT) s_y[tid] = g_yhl[(size_t)i * LAT + tid];
        __syncthreads();
        float x = 0.f;
#pragma unroll 8
        for (int u = 0; u < LAT; ++u)
            x = fmaf(s_y[u], Wd[u * BSZ + tid], x);
        g_What[(size_t)r * NDIM + jb * BSZ + tid] = x;
        __syncthreads();
    }
}

// ---------------------------------------------------------------------------
// kernOut: out = bias + x @ (W_hat * rn)^T, skipping exactly-zero k-blocks.
// ---------------------------------------------------------------------------
__global__ void kernOut(const float* __restrict__ x, const float* __restrict__ rn,
                        const float* __restrict__ bias, float* __restrict__ out) {
    __shared__ __align__(16) float xs[16][64];
    __shared__ __align__(16) float ws[16][64];
    __shared__ unsigned char shf[NB];

    int b0 = blockIdx.x * 64;
    int m0 = blockIdx.y * 64;
    int tid = threadIdx.x;

    if (tid < NB) {
        unsigned char f = 0;
        for (int mm = 0; mm < 64; ++mm) f |= g_flags[(m0 + mm) * NB + tid];
        shf[tid] = f;
    }
    __syncthreads();

    int tr = tid >> 4, tc = tid & 15;
    int l_r = tid >> 2, l_q = (tid & 3) * 4;

    float acc[4][4];
#pragma unroll
    for (int i = 0; i < 4; ++i)
#pragma unroll
        for (int q = 0; q < 4; ++q) acc[i][q] = 0.f;

    float rnm = rn[m0 + l_r];

    for (int jj = 0; jj < NB; ++jj) {
        if (!shf[jj]) continue;
        for (int k0 = 0; k0 < BSZ; k0 += 16) {
            float4 xv = *reinterpret_cast<const float4*>(x + (size_t)(b0 + l_r) * NDIM + jj * BSZ + k0 + l_q);
            xs[l_q + 0][l_r] = xv.x; xs[l_q + 1][l_r] = xv.y;
            xs[l_q + 2][l_r] = xv.z; xs[l_q + 3][l_r] = xv.w;
            // unflagged (m,jj) rows of W_hat may hold stale data; gate per-row
            float4 wv = make_float4(0.f, 0.f, 0.f, 0.f);
            if (g_flags[(m0 + l_r) * NB + jj])
                wv = *reinterpret_cast<const float4*>(g_What + (size_t)(m0 + l_r) * NDIM + jj * BSZ + k0 + l_q);
            ws[l_q + 0][l_r] = wv.x * rnm; ws[l_q + 1][l_r] = wv.y * rnm;
            ws[l_q + 2][l_r] = wv.z * rnm; ws[l_q + 3][l_r] = wv.w * rnm;
            __syncthreads();
#pragma unroll
            for (int kk = 0; kk < 16; ++kk) {
                float4 a4 = *reinterpret_cast<const float4*>(&xs[kk][tr * 4]);
                float4 b4 = *reinterpret_cast<const float4*>(&ws[kk][tc * 4]);
                float a[4] = {a4.x, a4.y, a4.z, a4.w};
                float b[4] = {b4.x, b4.y, b4.z, b4.w};
#pragma unroll
                for (int i = 0; i < 4; ++i)
#pragma unroll
                    for (int q = 0; q < 4; ++q)
                        acc[i][q] = fmaf(a[i], b[q], acc[i][q]);
            }
            __syncthreads();
        }
    }

#pragma unroll
    for (int i = 0; i < 4; ++i) {
        int b = b0 + tr * 4 + i;
#pragma unroll
        for (int q = 0; q < 4; ++q) {
            int m = m0 + tc * 4 + q;
            out[(size_t)b * NDIM + m] = bias[m] + acc[i][q];
        }
    }
}

// ---------------------------------------------------------------------------
// kernel_launch: inputs (metadata order): x, weight, bias, row_norm, L, We, Wd
// ---------------------------------------------------------------------------
extern "C" void kernel_launch(void* const* d_in, const int* in_sizes, int n_in,
                              void* d_out, int out_size) {
    (void)in_sizes; (void)n_in; (void)out_size;
    const float* x      = (const float*)d_in[0];
    const float* weight = (const float*)d_in[1];
    const float* bias   = (const float*)d_in[2];
    const float* rn     = (const float*)d_in[3];
    const float* L      = (const float*)d_in[4];
    const float* We     = (const float*)d_in[5];
    const float* Wd     = (const float*)d_in[6];
    float* out          = (float*)d_out;

    kernPrep<<<8224, 256>>>(weight, We);                  // [0] W split, WeT split
    kernG<<<dim3(32, 32), 128, 30720>>>(L, We);           // [1] full Mt
    kernGemmY<<<dim3(32, 16), 256, 40960>>>();            // [2] Y = W @ M (3-term fp16)
    kernH<<<dim3(32, 32), 256>>>(Wd);                     // [3] latent feedback H + cnt reset
    kernSteps<<<1024, 256>>>(rn);                         // [4] 32 steps in latent space
    kernWhat<<<1024, 128>>>(Wd);                          // [5] sparse W_hat blocks
    kernOut<<<dim3(64, 64), 256>>>(x, rn, bias, out);     // [6] output GEMM
}